// round 1
// baseline (speedup 1.0000x reference)
#include <cuda_runtime.h>

#define LOG2PI_F 1.8378770664093454f   // log(2*pi)
#define LOG2E_F  1.4426950408889634f   // log2(e)

// out[0 .. B*2K)        = density_norm  (pdf repeated per coordinate)
// out[B*2K .. 2*B*2K)   = eta * negexp_grad  (eta = 1)
__global__ __launch_bounds__(256)
void recovery_policy_kernel(
    const float* __restrict__ z,      // [B,K,2]
    const float* __restrict__ w,      // [K,C]
    const float* __restrict__ mu,     // [K,C,2]
    const float* __restrict__ cov,    // [K,C,2,2]
    const float* __restrict__ scale,  // [K,2]
    float* __restrict__ out,
    int B, int K, int C, int gradOff)
{
    const int k   = blockIdx.y;
    const int tid = threadIdx.x;

    __shared__ float4 s_p[128];   // i00, i01, i11, c2   (per component)
    __shared__ float2 s_m[128];   // mean
    __shared__ float2 s_scale;

    if (tid < C) {
        const int idx = k * C + tid;
        const float4 cv = ((const float4*)cov)[idx];      // a b c d (row-major 2x2)
        const float det  = cv.x * cv.w - cv.y * cv.z;
        const float rdet = 1.0f / det;
        const float i00 =  cv.w * rdet;
        const float i01 = -cv.y * rdet;                   // symmetric: i10 == i01
        const float i11 =  cv.x * rdet;
        // c2 = (log w - 0.5*log det - log(2pi)) * log2(e)   [exponent in base-2]
        const float c2 = (logf(w[idx]) - 0.5f * logf(det) - LOG2PI_F) * LOG2E_F;
        s_p[tid] = make_float4(i00, i01, i11, c2);
        s_m[tid] = ((const float2*)mu)[idx];
    }
    if (tid == 0) s_scale = ((const float2*)scale)[k];
    __syncthreads();

    const int b = blockIdx.x * blockDim.x + tid;
    if (b >= B) return;

    const float2 zz = ((const float2*)z)[(size_t)b * K + k];

    float pdf = 0.0f, g0 = 0.0f, g1 = 0.0f;
    #pragma unroll 16
    for (int c = 0; c < C; c++) {
        const float4 p = s_p[c];
        const float2 m = s_m[c];
        const float d0 = zz.x - m.x;
        const float d1 = zz.y - m.y;
        const float s0 = fmaf(p.x, d0, p.y * d1);   // Sigma^-1 * diff
        const float s1 = fmaf(p.y, d0, p.z * d1);
        const float maha = fmaf(d0, s0, d1 * s1);
        // comp = w * N(z; mu, Sigma) = 2^( -0.5*log2e*maha + c2 )
        const float e = exp2f(fmaf(maha, -0.5f * LOG2E_F, p.w));
        pdf += e;
        g0 = fmaf(e, s0, g0);
        g1 = fmaf(e, s1, g1);
    }

    // grad of pdf wrt z is -(sum comp*s); then unnormalize by latent scale
    g0 = -g0 * s_scale.x;
    g1 = -g1 * s_scale.y;

    // density_norm = sigmoid((pdf + eps)/tau), eps=-0.5 tau=0.5 -> sigmoid(2*pdf - 1)
    const float dn = 1.0f / (1.0f + expf(1.0f - 2.0f * pdf));

    const float nrm = sqrtf(g0 * g0 + g1 * g1);
    // mag = exp((5500 - nrm)/1100)
    const float mag = expf((5500.0f - nrm) * (1.0f / 1100.0f));
    const float r   = mag / nrm;

    ((float2*)out)[(size_t)b * K + k] = make_float2(dn, dn);
    ((float2*)(out + gradOff))[(size_t)b * K + k] = make_float2(g0 * r, g1 * r);
}

extern "C" void kernel_launch(void* const* d_in, const int* in_sizes, int n_in,
                              void* d_out, int out_size)
{
    const float* z     = (const float*)d_in[0];  // [B,K,2]
    const float* w     = (const float*)d_in[1];  // [K,C]
    const float* mu    = (const float*)d_in[2];  // [K,C,2]
    const float* cov   = (const float*)d_in[3];  // [K,C,2,2]
    const float* scale = (const float*)d_in[4];  // [K,2]
    float* out = (float*)d_out;

    const int K = in_sizes[4] / 2;
    const int C = in_sizes[1] / K;
    const int B = in_sizes[0] / (2 * K);
    const int gradOff = out_size / 2;            // second output tensor

    dim3 grid((B + 255) / 256, K);
    recovery_policy_kernel<<<grid, 256>>>(z, w, mu, cov, scale, out,
                                          B, K, C, gradOff);
}